// round 15
// baseline (speedup 1.0000x reference)
#include <cuda_runtime.h>

#define Bb 2
#define Nn 512
#define Ff 16
#define Dd 64
#define Hh 4
#define DhD 16
#define Cc 4
#define HIDD 256
#define NEGV (-9.0e15f)
#define MAXD 96
#define K2R 4

typedef unsigned long long u64;

__device__ __forceinline__ u64 pack2(float lo, float hi) {
    u64 r;
    asm("mov.b64 %0, {%1, %2};" : "=l"(r) : "f"(lo), "f"(hi));
    return r;
}
__device__ __forceinline__ void fma2(u64& d, u64 a, u64 b) {
    asm("fma.rn.f32x2 %0, %1, %2, %0;" : "+l"(d) : "l"(a), "l"(b));
}

__device__ __align__(16) float g_h[Bb*Nn*Dd];
__device__ __align__(16) float g_q[Bb*Hh*Nn*DhD];
__device__ __align__(16) float g_k[Bb*Hh*Nn*DhD];
__device__ __align__(16) float g_v[Bb*Hh*Nn*DhD];
__device__ __align__(16) float g_a[Bb*Nn*HIDD];
__device__ __align__(16) float g_bb[Bb*Nn*HIDD];
__device__ int g_cnt[Nn];
__device__ int g_js[Nn*MAXD];

// ---------------------------------------------------------------------------
// K1: one block per row, grid 1024 x 256 (best measured). f32x2 qkv.
// ---------------------------------------------------------------------------
__global__ void k1_embed_qkv(const float* __restrict__ x,
                             const float* __restrict__ adj,
                             const float* __restrict__ W_emb,
                             const float* __restrict__ Wq,
                             const float* __restrict__ Wk,
                             const float* __restrict__ Wv) {
    __shared__ float hsh[Dd];
    __shared__ __align__(16) float psh[3][16][Dd];
    const int t = threadIdx.x;
    const int row = blockIdx.x;
    const int b = row >> 9, n = row & (Nn - 1);

    // h = x @ W_emb (threads 0..63)
    if (t < Dd) {
        const float* xr = x + row * Ff;
        float acc = 0.f;
#pragma unroll
        for (int f = 0; f < Ff; f++)
            acc += __ldg(xr + f) * __ldg(W_emb + f * Dd + t);
        hsh[t] = acc;
        g_h[row * Dd + t] = acc;
    }

    // adjacency compaction: blocks 0..511, warp 1
    if (row < Nn && (t >= 32 && t < 64)) {
        const int lane = t - 32;
        const float4* arow4 = (const float4*)(adj + row * Nn);
        float4 a4[4];
#pragma unroll
        for (int s = 0; s < 4; s++) a4[s] = arow4[s * 32 + lane];
        int base = 0;
#pragma unroll
        for (int s = 0; s < 4; s++) {
            const float comp[4] = { a4[s].x, a4[s].y, a4[s].z, a4[s].w };
#pragma unroll
            for (int c = 0; c < 4; c++) {
                const bool hit = (comp[c] > 0.f);
                const unsigned bal = __ballot_sync(0xffffffffu, hit);
                if (hit) {
                    const int pos = base + __popc(bal & ((1u << lane) - 1u));
                    if (pos < MAXD) g_js[row * MAXD + pos] = (s * 32 + lane) * 4 + c;
                }
                base += __popc(bal);
            }
        }
        if (lane == 0) g_cnt[row] = (base < MAXD) ? base : MAXD;
    }
    __syncthreads();

    // qkv partials: float4/u64x2 columns, 16 segs x 4 d's, f32x2 FMA
    {
        const int c4 = t & 15;
        const int seg = t >> 4;
        u64 aq0 = 0, aq1 = 0, ak0 = 0, ak1 = 0, av0 = 0, av1 = 0;
#pragma unroll
        for (int dd = 0; dd < 4; dd++) {
            const int d = seg * 4 + dd;
            const float hv = hsh[d];
            const u64 h2 = pack2(hv, hv);
            const ulonglong2 wq = __ldg((const ulonglong2*)(Wq + d * Dd) + c4);
            const ulonglong2 wk = __ldg((const ulonglong2*)(Wk + d * Dd) + c4);
            const ulonglong2 wv = __ldg((const ulonglong2*)(Wv + d * Dd) + c4);
            fma2(aq0, h2, wq.x); fma2(aq1, h2, wq.y);
            fma2(ak0, h2, wk.x); fma2(ak1, h2, wk.y);
            fma2(av0, h2, wv.x); fma2(av1, h2, wv.y);
        }
        ulonglong2* p0 = (ulonglong2*)&psh[0][seg][c4 * 4];
        ulonglong2* p1 = (ulonglong2*)&psh[1][seg][c4 * 4];
        ulonglong2* p2 = (ulonglong2*)&psh[2][seg][c4 * 4];
        *p0 = make_ulonglong2(aq0, aq1);
        *p1 = make_ulonglong2(ak0, ak1);
        *p2 = make_ulonglong2(av0, av1);
    }
    __syncthreads();

    if (t < 192) {
        const int m = t >> 6;
        const int c = t & 63;
        float s = 0.f;
#pragma unroll
        for (int seg = 0; seg < 16; seg++) s += psh[m][seg][c];
        const int hd = c >> 4, dh = c & 15;
        const int idx = ((b * Hh + hd) * Nn + n) * DhD + dh;
        if (m == 0) g_q[idx] = s;
        else if (m == 1) g_k[idx] = s;
        else g_v[idx] = s;
    }
}

// ---------------------------------------------------------------------------
// K2: grid 256 x 512 threads, 4 rows/block + NEG fill at entry. f32x2 GEMMs.
// ---------------------------------------------------------------------------
__global__ void k2_attn_ff(const float* __restrict__ Wo,
                           const float* __restrict__ W1,
                           const float* __restrict__ b1,
                           float* __restrict__ out) {
    __shared__ int jsh[K2R][MAXD];
    __shared__ int csh[K2R];
    __shared__ float wsh[K2R][Hh][MAXD];
    __shared__ float osh[K2R][Dd];
    __shared__ float ysh[K2R][Dd];
    __shared__ __align__(16) float4 pshy[8][K2R][16];
    __shared__ __align__(16) float4 pshab[2][2][K2R][64];

    const int t = threadIdx.x;
    const int warp = t >> 5, lane = t & 31;
    const int row0 = blockIdx.x * K2R;
    const int b = row0 >> 9, n0 = row0 & (Nn - 1);

    // NEG fill: 2048 float4, 4/thread
    {
        const float4 neg4 = make_float4(NEGV, NEGV, NEGV, NEGV);
#pragma unroll
        for (int s = 0; s < 4; s++) {
            const int e = s * 512 + t;
            const int r = e >> 9;
            const int rem = e & 511;
            const int ch = rem >> 7, col4 = rem & 127;
            float4* rp = (float4*)(out + (((size_t)(b * Cc + ch) * Nn + (n0 + r)) * Nn));
            rp[col4] = neg4;
        }
    }

    // stage neighbor lists
    if (warp < K2R) {
        const int r = warp;
        const int i = n0 + r;
        const int cnt = g_cnt[i];
        if (lane == 0) csh[r] = cnt;
        for (int e = lane; e < cnt; e += 32) jsh[r][e] = g_js[i * MAXD + e];
    }
    __syncthreads();

    // softmax weights: 16 warps = (r = warp&3, hd = warp>>2)
    {
        const int r = warp & 3;
        const int hd = warp >> 2;
        const int i = n0 + r;
        const int cnt = csh[r];
        const int nch = (cnt + 31) >> 5;

        const float4* qp = (const float4*)(g_q + ((b * Hh + hd) * Nn + i) * DhD);
        const float4 q0 = __ldg(qp), q1 = __ldg(qp + 1),
                     q2 = __ldg(qp + 2), q3 = __ldg(qp + 3);
        const float* kbase = g_k + (b * Hh + hd) * Nn * DhD;

        float sc[3];
        float m = -3.0e38f;
#pragma unroll
        for (int c = 0; c < 3; c++) {
            sc[c] = -3.0e38f;
            if (c < nch) {
                const int e = c * 32 + lane;
                if (e < cnt) {
                    const float4* kp = (const float4*)(kbase + jsh[r][e] * DhD);
                    const float4 k0 = kp[0], k1 = kp[1], k2 = kp[2], k3 = kp[3];
                    float dot = q0.x*k0.x + q0.y*k0.y + q0.z*k0.z + q0.w*k0.w;
                    dot += q1.x*k1.x + q1.y*k1.y + q1.z*k1.z + q1.w*k1.w;
                    dot += q2.x*k2.x + q2.y*k2.y + q2.z*k2.z + q2.w*k2.w;
                    dot += q3.x*k3.x + q3.y*k3.y + q3.z*k3.z + q3.w*k3.w;
                    sc[c] = dot * 0.25f;
                }
                m = fmaxf(m, sc[c]);
            }
        }
#pragma unroll
        for (int o = 16; o > 0; o >>= 1)
            m = fmaxf(m, __shfl_xor_sync(0xffffffffu, m, o));

        float sum = 0.f;
#pragma unroll
        for (int c = 0; c < 3; c++) {
            sc[c] = expf(sc[c] - m);
            sum += sc[c];
        }
#pragma unroll
        for (int o = 16; o > 0; o >>= 1)
            sum += __shfl_xor_sync(0xffffffffu, sum, o);
        const float inv = 1.f / sum;
#pragma unroll
        for (int c = 0; c < 3; c++) {
            if (c < nch) {
                const int e = c * 32 + lane;
                if (e < cnt) wsh[r][hd][e] = sc[c] * inv;
            }
        }
    }
    __syncthreads();

    // o[r][hd][d]: 256 items
    if (t < K2R * Hh * DhD) {
        const int r = t >> 6;
        const int hd = (t >> 4) & 3;
        const int d = t & 15;
        const int cnt = csh[r];
        const float* vbase = g_v + (b * Hh + hd) * Nn * DhD + d;
        const float* wrow = wsh[r][hd];
        const int* jrow = jsh[r];

        float ov = 0.f;
        int e = 0;
        for (; e + 4 <= cnt; e += 4) {
            const float v0 = vbase[jrow[e] * DhD];
            const float v1 = vbase[jrow[e+1] * DhD];
            const float v2 = vbase[jrow[e+2] * DhD];
            const float v3 = vbase[jrow[e+3] * DhD];
            ov += wrow[e] * v0 + wrow[e+1] * v1 + wrow[e+2] * v2 + wrow[e+3] * v3;
        }
        for (; e < cnt; e++)
            ov += wrow[e] * vbase[jrow[e] * DhD];
        osh[r][hd * DhD + d] = ov;
    }
    __syncthreads();

    // y partials: (c4:16, r:4, seg:8), chain 8, f32x2
    {
        const int c4 = t & 15;
        const int r = (t >> 4) & 3;
        const int seg = t >> 6;
        u64 a0 = 0, a1 = 0;
#pragma unroll
        for (int dd = 0; dd < 8; dd++) {
            const int d = seg * 8 + dd;
            const float o_ = osh[r][d];
            const u64 o2 = pack2(o_, o_);
            const ulonglong2 w2 = __ldg((const ulonglong2*)(Wo + d * Dd) + c4);
            fma2(a0, o2, w2.x); fma2(a1, o2, w2.y);
        }
        *(ulonglong2*)&pshy[seg][r][c4] = make_ulonglong2(a0, a1);
    }
    __syncthreads();

    // y finalize
    if (t < 64) {
        const int c4 = t & 15;
        const int r = t >> 4;
        float4 acc = *(const float4*)&g_h[(row0 + r) * Dd + c4 * 4];
#pragma unroll
        for (int seg = 0; seg < 8; seg++) {
            const float4 p = pshy[seg][r][c4];
            acc.x += p.x; acc.y += p.y; acc.z += p.z; acc.w += p.w;
        }
        *(float4*)&ysh[r][c4 * 4] = acc;
    }
    __syncthreads();

    // a/b partials: (c4:64, ab:2, rpair:2, seg:2), chain 32, 2 rows, f32x2
    {
        const int c4 = t & 63;
        const int ab = (t >> 6) & 1;
        const int rp = (t >> 7) & 1;
        const int seg = t >> 8;
        const int rA = rp * 2, rB = rp * 2 + 1;
        const float* Wbase = W1 + (size_t)(ab * Dd + seg * 32) * HIDD;
        u64 aA0 = 0, aA1 = 0, aB0 = 0, aB1 = 0;
#pragma unroll 8
        for (int dd = 0; dd < 32; dd++) {
            const ulonglong2 w2 = __ldg((const ulonglong2*)(Wbase + dd * HIDD) + c4);
            const int d = seg * 32 + dd;
            const u64 yA2 = pack2(ysh[rA][d], ysh[rA][d]);
            const u64 yB2 = pack2(ysh[rB][d], ysh[rB][d]);
            fma2(aA0, yA2, w2.x); fma2(aA1, yA2, w2.y);
            fma2(aB0, yB2, w2.x); fma2(aB1, yB2, w2.y);
        }
        *(ulonglong2*)&pshab[seg][ab][rA][c4] = make_ulonglong2(aA0, aA1);
        *(ulonglong2*)&pshab[seg][ab][rB][c4] = make_ulonglong2(aB0, aB1);
    }
    __syncthreads();

    // a/b finalize: 512 float4, 1/thread
    {
        const int c4 = t & 63;
        const int r = (t >> 6) & 3;
        const int ab = t >> 8;
        float4 p0 = pshab[0][ab][r][c4];
        const float4 p1 = pshab[1][ab][r][c4];
        p0.x += p1.x; p0.y += p1.y; p0.z += p1.z; p0.w += p1.w;
        if (ab == 0) {
            const float4 bias = __ldg((const float4*)b1 + c4);
            p0.x += bias.x; p0.y += bias.y; p0.z += bias.z; p0.w += bias.w;
            *(float4*)&g_a[(row0 + r) * HIDD + c4 * 4] = p0;
        } else {
            *(float4*)&g_bb[(row0 + r) * HIDD + c4 * 4] = p0;
        }
    }
}

// ---------------------------------------------------------------------------
// K3: sparse scatter, 2 entries per iteration (interleaved reduce trees).
// ---------------------------------------------------------------------------
__global__ void k3_out(const float* __restrict__ W2,
                       const float* __restrict__ b2,
                       float* __restrict__ out) {
    const int row = blockIdx.x;
    const int b = row >> 9, i = row & (Nn - 1);
    const int warp = threadIdx.x >> 5;
    const int lane = threadIdx.x & 31;

    const int cnt = g_cnt[i];
    const int* js = g_js + i * MAXD;
    const int h0 = lane * 8;

    const float4* ap = (const float4*)(g_a + row * HIDD + h0);
    const float4 a0 = ap[0], a1 = ap[1];
    float4 w[8];
#pragma unroll
    for (int k = 0; k < 8; k++) w[k] = __ldg((const float4*)W2 + h0 + k);
    const float b20 = __ldg(b2 + 0), b21 = __ldg(b2 + 1);
    const float b22 = __ldg(b2 + 2), b23 = __ldg(b2 + 3);

#define PAIR_BODY(AV, BV, WK, P, Q) \
        tt = fmaxf((AV) + (BV), 0.f); \
        P##0 += tt * (WK).x; P##1 += tt * (WK).y; P##2 += tt * (WK).z; P##3 += tt * (WK).w;

    for (int e0 = warp * 2; e0 < cnt; e0 += 8) {
        const int e1 = e0 + 1;
        const bool has1 = (e1 < cnt);
        const int jA = js[e0];
        const int jB = has1 ? js[e1] : jA;

        const float4* bpA = (const float4*)(g_bb + ((size_t)(b * Nn + jA)) * HIDD + h0);
        const float4* bpB = (const float4*)(g_bb + ((size_t)(b * Nn + jB)) * HIDD + h0);
        const float4 bA0 = bpA[0], bA1 = bpA[1];
        const float4 bB0 = bpB[0], bB1 = bpB[1];

        float pA0 = 0.f, pA1 = 0.f, pA2 = 0.f, pA3 = 0.f;
        float pB0 = 0.f, pB1 = 0.f, pB2 = 0.f, pB3 = 0.f;
        float tt;
        PAIR_BODY(a0.x, bA0.x, w[0], pA, )
        PAIR_BODY(a0.x, bB0.x, w[0], pB, )
        PAIR_BODY(a0.y, bA0.y, w[1], pA, )
        PAIR_BODY(a0.y, bB0.y, w[1], pB, )
        PAIR_BODY(a0.z, bA0.z, w[2], pA, )
        PAIR_BODY(a0.z, bB0.z, w[2], pB, )
        PAIR_BODY(a0.w, bA0.w, w[3], pA, )
        PAIR_BODY(a0.w, bB0.w, w[3], pB, )
        PAIR_BODY(a1.x, bA1.x, w[4], pA, )
        PAIR_BODY(a1.x, bB1.x, w[4], pB, )
        PAIR_BODY(a1.y, bA1.y, w[5], pA, )
        PAIR_BODY(a1.y, bB1.y, w[5], pB, )
        PAIR_BODY(a1.z, bA1.z, w[6], pA, )
        PAIR_BODY(a1.z, bB1.z, w[6], pB, )
        PAIR_BODY(a1.w, bA1.w, w[7], pA, )
        PAIR_BODY(a1.w, bB1.w, w[7], pB, )

        // interleaved butterfly reduces (two independent trees)
#pragma unroll
        for (int o = 16; o > 0; o >>= 1) {
            pA0 += __shfl_xor_sync(0xffffffffu, pA0, o);
            pB0 += __shfl_xor_sync(0xffffffffu, pB0, o);
            pA1 += __shfl_xor_sync(0xffffffffu, pA1, o);
            pB1 += __shfl_xor_sync(0xffffffffu, pB1, o);
            pA2 += __shfl_xor_sync(0xffffffffu, pA2, o);
            pB2 += __shfl_xor_sync(0xffffffffu, pB2, o);
            pA3 += __shfl_xor_sync(0xffffffffu, pA3, o);
            pB3 += __shfl_xor_sync(0xffffffffu, pB3, o);
        }
        if (lane == 0) {
            out[(((size_t)(b * Cc + 0) * Nn + i) * Nn) + jA] = pA0 + b20;
            out[(((size_t)(b * Cc + 1) * Nn + i) * Nn) + jA] = pA1 + b21;
            out[(((size_t)(b * Cc + 2) * Nn + i) * Nn) + jA] = pA2 + b22;
            out[(((size_t)(b * Cc + 3) * Nn + i) * Nn) + jA] = pA3 + b23;
            if (has1) {
                out[(((size_t)(b * Cc + 0) * Nn + i) * Nn) + jB] = pB0 + b20;
                out[(((size_t)(b * Cc + 1) * Nn + i) * Nn) + jB] = pB1 + b21;
                out[(((size_t)(b * Cc + 2) * Nn + i) * Nn) + jB] = pB2 + b22;
                out[(((size_t)(b * Cc + 3) * Nn + i) * Nn) + jB] = pB3 + b23;
            }
        }
    }
#undef PAIR_BODY
}

// ---------------------------------------------------------------------------
extern "C" void kernel_launch(void* const* d_in, const int* in_sizes, int n_in,
                              void* d_out, int out_size) {
    const float* x     = (const float*)d_in[0];
    const float* adj   = (const float*)d_in[1];
    const float* W_emb = (const float*)d_in[2];
    const float* Wq    = (const float*)d_in[3];
    const float* Wk    = (const float*)d_in[4];
    const float* Wv    = (const float*)d_in[5];
    const float* Wo    = (const float*)d_in[6];
    const float* W1    = (const float*)d_in[7];
    const float* b1    = (const float*)d_in[8];
    const float* W2    = (const float*)d_in[9];
    const float* b2    = (const float*)d_in[10];
    float* out = (float*)d_out;

    k1_embed_qkv<<<Bb * Nn, 256>>>(x, adj, W_emb, Wq, Wk, Wv);
    k2_attn_ff<<<(Bb * Nn) / K2R, 512>>>(Wo, W1, b1, out);
    k3_out<<<Bb * Nn, 128>>>(W2, b2, out);
}